// round 17
// baseline (speedup 1.0000x reference)
#include <cuda_runtime.h>
#include <cstdint>

#define N_NODES 128
#define F_IN    128
#define HID     64
#define N_CLS   40
#define NB      4
#define AP      72    // u32 pitch, A-side arrays (8-bank shift: conflict-free LDS.64)
#define BP      72    // u32 pitch, B-side arrays

// Precomputed A_norm^2 (scratch)
__device__ float g_A2[N_NODES * N_NODES];

// ---------------------------------------------------------------------------
// helpers
// ---------------------------------------------------------------------------
__device__ __forceinline__ unsigned pack_split(float v0, float v1, unsigned& mid) {
    unsigned h;
    asm("cvt.rn.bf16x2.f32 %0, %1, %2;" : "=r"(h) : "f"(v1), "f"(v0)); // first src -> upper half
    float h0 = __uint_as_float(h << 16);
    float h1 = __uint_as_float(h & 0xffff0000u);
    float m0 = v0 - h0;
    float m1 = v1 - h1;
    asm("cvt.rn.bf16x2.f32 %0, %1, %2;" : "=r"(mid) : "f"(m1), "f"(m0));
    return h;
}

// pair-permutation: frag pairs (8kk+tg, 8kk+tg+4) land in adjacent u32 slots
__device__ __forceinline__ int perm(int p) {
    int t = p & 7;
    return (p & ~7) | ((t & 3) << 1) | (t >> 2);
}

// Non-volatile: let ptxas schedule/pipeline HMMAs freely.
__device__ __forceinline__ void mma_bf16(float* c, const unsigned* a, unsigned b0, unsigned b1) {
    asm("mma.sync.aligned.m16n8k16.row.col.f32.bf16.bf16.f32 "
        "{%0,%1,%2,%3}, {%4,%5,%6,%7}, {%8,%9}, {%0,%1,%2,%3};"
        : "+f"(c[0]), "+f"(c[1]), "+f"(c[2]), "+f"(c[3])
        : "r"(a[0]), "r"(a[1]), "r"(a[2]), "r"(a[3]), "r"(b0), "r"(b1));
}

__device__ __forceinline__ int tril_idx(int i, int j) {
    int hi = i > j ? i : j;
    int lo = i > j ? j : i;
    return hi * (hi + 1) / 2 + lo;
}

// ---------------------------------------------------------------------------
// Prologue kernel: A2 = (D^-1/2 (A+I) D^-1/2)^2
// ---------------------------------------------------------------------------
__global__ void __launch_bounds__(128, 8) build_a2_kernel(const float* __restrict__ ew)
{
    __shared__ float dinv[N_NODES];
    __shared__ float rowi[N_NODES];
    const int i = blockIdx.x;
    const int j = threadIdx.x;

    float s = 0.f;
#pragma unroll 8
    for (int k = 0; k < N_NODES; ++k)
        s += ew[tril_idx(j, k)] + (k == j ? 1.f : 0.f);
    dinv[j] = (s > 0.f) ? rsqrtf(s) : 0.f;
    __syncthreads();

    rowi[j] = dinv[i] * (ew[tril_idx(i, j)] + (i == j ? 1.f : 0.f)) * dinv[j];
    __syncthreads();

    const float dj = dinv[j];
    float acc = 0.f;
#pragma unroll 8
    for (int k = 0; k < N_NODES; ++k) {
        float akj = dinv[k] * (ew[tril_idx(k, j)] + (k == j ? 1.f : 0.f)) * dj;
        acc += rowi[k] * akj;
    }
    g_A2[i * N_NODES + j] = acc;
}

// ---------------------------------------------------------------------------
// Main fused kernel. 256 thr / 8 warps, warp tile 32(M)x32(N).
// bf16 split GEMMs (hh+hm+mh). Pair-permuted layouts -> LDS.64 frag loads;
// Y pre-split+transposed at store; X(it+1) split interleaved into GEMM2;
// FC(it-1) deferred into head of GEMM1. 2 syncthreads per batch.
// ---------------------------------------------------------------------------
struct SMem {
    unsigned Xh[N_NODES][AP];     // X pairs (perm cols), hi
    unsigned Xm[N_NODES][AP];
    unsigned A2h[N_NODES][AP];
    unsigned A2m[N_NODES][AP];
    unsigned Wth[HID][BP];        // W transposed: [n][perm(kpair)]
    unsigned Wtm[HID][BP];
    unsigned Yth[HID][BP];        // Y transposed+pre-split: [n][perm(nodepair)]
    unsigned Ytm[HID][BP];
    float pooled[2][HID];
    float lb[HID];
    float cw[N_NODES];
};

__global__ void __launch_bounds__(256, 1)
dgcnn_main(const float* __restrict__ x,
           const float* __restrict__ lin_w,
           const float* __restrict__ lin_b,
           const float* __restrict__ conv_w,
           const float* __restrict__ conv_b,
           const float* __restrict__ fc_w,
           const float* __restrict__ fc_b,
           float* __restrict__ out,
           int Btot)
{
    extern __shared__ char smraw[];
    SMem* sm = reinterpret_cast<SMem*>(smraw);

    const int tid  = threadIdx.x;
    const int lane = tid & 31;
    const int warp = tid >> 5;
    const int g    = lane >> 2;
    const int tg   = lane & 3;
    const int wM   = warp >> 1;   // 0..3
    const int wN   = warp & 1;    // 0..1
    const int bbase = blockIdx.x * NB;

    // ---- prologue: A2 -> perm-split ----
#pragma unroll
    for (int q = 0; q < 32; ++q) {
        int p = tid + (q << 8);
        int r = p >> 6, c = p & 63;
        float2 v = *reinterpret_cast<const float2*>(g_A2 + r * N_NODES + 2 * c);
        unsigned m, h = pack_split(v.x, v.y, m);
        sm->A2h[r][perm(c)] = h;
        sm->A2m[r][perm(c)] = m;
    }
    // ---- prologue: W -> transposed perm-split ----
#pragma unroll
    for (int q = 0; q < 16; ++q) {
        int p = tid + (q << 8);
        int kp = p >> 6, n = p & 63;
        float v0 = lin_w[(2 * kp) * HID + n];
        float v1 = lin_w[(2 * kp + 1) * HID + n];
        unsigned m, h = pack_split(v0, v1, m);
        sm->Wth[n][perm(kp)] = h;
        sm->Wtm[n][perm(kp)] = m;
    }
    if (tid < HID)     sm->lb[tid] = lin_b[tid];
    if (tid < N_NODES) sm->cw[tid] = conv_w[tid];
    if (tid < 2 * HID) sm->pooled[tid >> 6][tid & 63] = 0.f;

    // ---- prologue: load + split X(0) ----
    uint4 xr[16];
    if (bbase < Btot) {
        const uint4* xb = (const uint4*)(x + (size_t)bbase * (N_NODES * F_IN));
#pragma unroll
        for (int c = 0; c < 16; ++c) xr[c] = __ldg(xb + (c << 8) + tid);
#pragma unroll
        for (int c = 0; c < 16; ++c) {
            int i4 = tid + (c << 8);
            int r = i4 >> 5, p0 = (i4 & 31) << 1;
            float4 v = *(float4*)&xr[c];
            unsigned m0, m1;
            unsigned h0 = pack_split(v.x, v.y, m0);
            unsigned h1 = pack_split(v.z, v.w, m1);
            sm->Xh[r][perm(p0)]     = h0;  sm->Xm[r][perm(p0)]     = m0;
            sm->Xh[r][perm(p0 + 1)] = h1;  sm->Xm[r][perm(p0 + 1)] = m1;
        }
    }
    __syncthreads();

#pragma unroll 1
    for (int it = 0; it < NB; ++it) {
        const int b = bbase + it;
        if (b >= Btot) break;
        const bool haveNext = (it + 1 < NB) && (b + 1 < Btot);

        // ---- issue LDG for X(it+1) ----
        if (haveNext) {
            const uint4* xb = (const uint4*)(x + (size_t)(b + 1) * (N_NODES * F_IN));
#pragma unroll
            for (int c = 0; c < 16; ++c) xr[c] = __ldg(xb + (c << 8) + tid);
        }

        // ---- deferred FC(it-1): warps 0-1 only ----
        if (it > 0 && tid < N_CLS) {
            const float* pl = sm->pooled[(it - 1) & 1];
            float cb = conv_b[0];
            float o = fc_b[tid];
#pragma unroll
            for (int h = 0; h < HID; ++h) {
                float ph = fmaxf(pl[h] + cb, 0.f);
                o += ph * __ldg(fc_w + h * N_CLS + tid);
            }
            out[(size_t)(b - 1) * N_CLS + tid] = o;
        }
        if (tid < HID) sm->pooled[it & 1][tid] = 0.f;

        float acc[2][4][4];

        // ============ GEMM1: Y = X @ W  (LDS.64 frags only) =================
#pragma unroll
        for (int mt = 0; mt < 2; ++mt)
#pragma unroll
            for (int nt = 0; nt < 4; ++nt)
#pragma unroll
                for (int j = 0; j < 4; ++j) acc[mt][nt][j] = 0.f;

#pragma unroll
        for (int kk = 0; kk < 8; ++kk) {
            const int kc = 8 * kk + 2 * tg;   // perm-space column
            unsigned ah[2][4], am[2][4], bh[4][2], bm[4][2];
#pragma unroll
            for (int mt = 0; mt < 2; ++mt) {
                int row = wM * 32 + mt * 16 + g;
                uint2 hl = *(const uint2*)&sm->Xh[row][kc];
                uint2 hh = *(const uint2*)&sm->Xh[row + 8][kc];
                uint2 ml = *(const uint2*)&sm->Xm[row][kc];
                uint2 mh = *(const uint2*)&sm->Xm[row + 8][kc];
                ah[mt][0] = hl.x; ah[mt][1] = hh.x; ah[mt][2] = hl.y; ah[mt][3] = hh.y;
                am[mt][0] = ml.x; am[mt][1] = mh.x; am[mt][2] = ml.y; am[mt][3] = mh.y;
            }
#pragma unroll
            for (int nt = 0; nt < 4; ++nt) {
                int n = wN * 32 + nt * 8 + g;
                uint2 bv = *(const uint2*)&sm->Wth[n][kc];
                uint2 mv = *(const uint2*)&sm->Wtm[n][kc];
                bh[nt][0] = bv.x; bh[nt][1] = bv.y;
                bm[nt][0] = mv.x; bm[nt][1] = mv.y;
            }
#pragma unroll
            for (int nt = 0; nt < 4; ++nt) {
                mma_bf16(acc[0][nt], ah[0], bh[nt][0], bh[nt][1]);
                mma_bf16(acc[1][nt], ah[1], bh[nt][0], bh[nt][1]);
            }
#pragma unroll
            for (int nt = 0; nt < 4; ++nt) {
                mma_bf16(acc[0][nt], ah[0], bm[nt][0], bm[nt][1]);
                mma_bf16(acc[1][nt], ah[1], bm[nt][0], bm[nt][1]);
            }
#pragma unroll
            for (int nt = 0; nt < 4; ++nt) {
                mma_bf16(acc[0][nt], am[0], bh[nt][0], bh[nt][1]);
                mma_bf16(acc[1][nt], am[1], bh[nt][0], bh[nt][1]);
            }
        }

        // ---- store Y: pair rows via shfl, pre-split, transposed ----
#pragma unroll
        for (int mt = 0; mt < 2; ++mt) {
#pragma unroll
            for (int nt = 0; nt < 4; ++nt) {
                float c0 = acc[mt][nt][0], c1 = acc[mt][nt][1];
                float c2 = acc[mt][nt][2], c3 = acc[mt][nt][3];
                float x0 = __shfl_xor_sync(0xffffffffu, c0, 4);
                float x1 = __shfl_xor_sync(0xffffffffu, c1, 4);
                float x2 = __shfl_xor_sync(0xffffffffu, c2, 4);
                float x3 = __shfl_xor_sync(0xffffffffu, c3, 4);
                int col0 = wN * 32 + nt * 8 + 2 * tg;
                if ((g & 1) == 0) {
                    int pi = perm(wM * 16 + mt * 8 + (g >> 1));
                    unsigned m, h;
                    h = pack_split(c0, x0, m);
                    sm->Yth[col0][pi] = h;     sm->Ytm[col0][pi] = m;
                    h = pack_split(c1, x1, m);
                    sm->Yth[col0 + 1][pi] = h; sm->Ytm[col0 + 1][pi] = m;
                } else {
                    int pi = perm(wM * 16 + mt * 8 + 4 + (g >> 1));
                    unsigned m, h;
                    h = pack_split(x2, c2, m);
                    sm->Yth[col0][pi] = h;     sm->Ytm[col0][pi] = m;
                    h = pack_split(x3, c3, m);
                    sm->Yth[col0 + 1][pi] = h; sm->Ytm[col0 + 1][pi] = m;
                }
            }
        }
        __syncthreads();            // Yt ready; Xs(it) free for overwrite

        // ============ GEMM2: Z = A2 @ Y, X(it+1) split interleaved ==========
#pragma unroll
        for (int mt = 0; mt < 2; ++mt)
#pragma unroll
            for (int nt = 0; nt < 4; ++nt)
#pragma unroll
                for (int j = 0; j < 4; ++j) acc[mt][nt][j] = 0.f;

#pragma unroll
        for (int kk = 0; kk < 8; ++kk) {
            if (haveNext) {
#pragma unroll
                for (int cc2 = 0; cc2 < 2; ++cc2) {
                    int c = 2 * kk + cc2;
                    int i4 = tid + (c << 8);
                    int r = i4 >> 5, p0 = (i4 & 31) << 1;
                    float4 v = *(float4*)&xr[c];
                    unsigned m0, m1;
                    unsigned h0 = pack_split(v.x, v.y, m0);
                    unsigned h1 = pack_split(v.z, v.w, m1);
                    sm->Xh[r][perm(p0)]     = h0;  sm->Xm[r][perm(p0)]     = m0;
                    sm->Xh[r][perm(p0 + 1)] = h1;  sm->Xm[r][perm(p0 + 1)] = m1;
                }
            }
            const int kc = 8 * kk + 2 * tg;
            unsigned ah[2][4], am[2][4], bh[4][2], bm[4][2];
#pragma unroll
            for (int mt = 0; mt < 2; ++mt) {
                int row = wM * 32 + mt * 16 + g;
                uint2 hl = *(const uint2*)&sm->A2h[row][kc];
                uint2 hh = *(const uint2*)&sm->A2h[row + 8][kc];
                uint2 ml = *(const uint2*)&sm->A2m[row][kc];
                uint2 mh = *(const uint2*)&sm->A2m[row + 8][kc];
                ah[mt][0] = hl.x; ah[mt][1] = hh.x; ah[mt][2] = hl.y; ah[mt][3] = hh.y;
                am[mt][0] = ml.x; am[mt][1] = mh.x; am[mt][2] = ml.y; am[mt][3] = mh.y;
            }
#pragma unroll
            for (int nt = 0; nt < 4; ++nt) {
                int n = wN * 32 + nt * 8 + g;
                uint2 bv = *(const uint2*)&sm->Yth[n][kc];
                uint2 mv = *(const uint2*)&sm->Ytm[n][kc];
                bh[nt][0] = bv.x; bh[nt][1] = bv.y;
                bm[nt][0] = mv.x; bm[nt][1] = mv.y;
            }
#pragma unroll
            for (int nt = 0; nt < 4; ++nt) {
                mma_bf16(acc[0][nt], ah[0], bh[nt][0], bh[nt][1]);
                mma_bf16(acc[1][nt], ah[1], bh[nt][0], bh[nt][1]);
            }
#pragma unroll
            for (int nt = 0; nt < 4; ++nt) {
                mma_bf16(acc[0][nt], ah[0], bm[nt][0], bm[nt][1]);
                mma_bf16(acc[1][nt], ah[1], bm[nt][0], bm[nt][1]);
            }
#pragma unroll
            for (int nt = 0; nt < 4; ++nt) {
                mma_bf16(acc[0][nt], am[0], bh[nt][0], bh[nt][1]);
                mma_bf16(acc[1][nt], am[1], bh[nt][0], bh[nt][1]);
            }
        }

        // ================= epilogue: bias+relu, conv_w pooling ===============
        float p[8];
#pragma unroll
        for (int i = 0; i < 8; ++i) p[i] = 0.f;
#pragma unroll
        for (int mt = 0; mt < 2; ++mt) {
            int r = wM * 32 + mt * 16 + g;
            float c0 = sm->cw[r], c1 = sm->cw[r + 8];
#pragma unroll
            for (int nt = 0; nt < 4; ++nt) {
                int cc = wN * 32 + nt * 8 + 2 * tg;
                float l0 = sm->lb[cc], l1 = sm->lb[cc + 1];
                p[2 * nt]     += fmaxf(acc[mt][nt][0] + l0, 0.f) * c0
                               + fmaxf(acc[mt][nt][2] + l0, 0.f) * c1;
                p[2 * nt + 1] += fmaxf(acc[mt][nt][1] + l1, 0.f) * c0
                               + fmaxf(acc[mt][nt][3] + l1, 0.f) * c1;
            }
        }
#pragma unroll
        for (int i = 0; i < 8; ++i) {
            p[i] += __shfl_xor_sync(0xffffffffu, p[i], 4);
            p[i] += __shfl_xor_sync(0xffffffffu, p[i], 8);
            p[i] += __shfl_xor_sync(0xffffffffu, p[i], 16);
        }
        if (lane < 4) {
            float* pl = sm->pooled[it & 1];
#pragma unroll
            for (int nt = 0; nt < 4; ++nt) {
                atomicAdd(&pl[wN * 32 + nt * 8 + 2 * lane],     p[2 * nt]);
                atomicAdd(&pl[wN * 32 + nt * 8 + 2 * lane + 1], p[2 * nt + 1]);
            }
        }
        __syncthreads();            // pooled(it) done; Xs(it+1) ready
    }

    // ---- tail FC for the last batch ----
    {
        int nb_done = min(NB, Btot - bbase);
        if (nb_done > 0 && tid < N_CLS) {
            int itl = nb_done - 1;
            const float* pl = sm->pooled[itl & 1];
            float cb = conv_b[0];
            float o = fc_b[tid];
#pragma unroll
            for (int h = 0; h < HID; ++h) {
                float ph = fmaxf(pl[h] + cb, 0.f);
                o += ph * __ldg(fc_w + h * N_CLS + tid);
            }
            out[(size_t)(bbase + itl) * N_CLS + tid] = o;
        }
    }
}

// ---------------------------------------------------------------------------
extern "C" void kernel_launch(void* const* d_in, const int* in_sizes, int n_in,
                              void* d_out, int out_size)
{
    const float* x   = (const float*)d_in[0];
    const float* ew  = (const float*)d_in[1];
    const float* lw  = (const float*)d_in[2];
    const float* lb  = (const float*)d_in[3];
    const float* cw  = (const float*)d_in[4];
    const float* cb  = (const float*)d_in[5];
    const float* fw  = (const float*)d_in[6];
    const float* fb  = (const float*)d_in[7];
    float* outp      = (float*)d_out;

    const int Btot = in_sizes[0] / (N_NODES * F_IN);

    build_a2_kernel<<<N_NODES, N_NODES>>>(ew);

    cudaFuncSetAttribute(dgcnn_main, cudaFuncAttributeMaxDynamicSharedMemorySize,
                         (int)sizeof(SMem));
    const int grid = (Btot + NB - 1) / NB;
    dgcnn_main<<<grid, 256, sizeof(SMem)>>>(x, lw, lb, cw, cb, fw, fb, outp, Btot);
}